// round 10
// baseline (speedup 1.0000x reference)
#include <cuda_runtime.h>
#include <cuda_bf16.h>
#include <cstdint>

// Problem constants
#define DIMD 256
#define KAT  512
#define NCOL 65536
#define NB   64          // prep CTAs (barrier group)
#define NCONV 84         // converter CTAs (NB+NCONV = 148 SMs, all co-resident)
#define NDUAL 6          // dual Newton-Schulz passes (then one final Y-only pass)

// Chebyshev degree-1 start for Newton-Schulz (residual 0.865 on [30,1600])
#define A_COEF 4.57720e-3f
#define B_COEF (-2.80809e-6f)
#define NODIAG (-1000000)

// ---------------------------------------------------------------------------
// Device scratch (no allocations allowed)
// ---------------------------------------------------------------------------
__device__ float g_G[DIMD * DIMD];
__device__ float g_Y[2 * DIMD * DIMD];    // Y ping-pong
__device__ float g_Z[2 * DIMD * DIMD];    // Z = G*Y ping-pong
__device__ unsigned g_bar = 0;            // monotone grid barrier

// Pre-swizzled bf16 images (XOR swizzle within 128B rows):
// A: per (ntile 0..511, dchunk 0..3): [split 2][128 n][64 d] = 32768 B each
__device__ __align__(1024) __nv_bfloat16 g_Aimg[512 * 4 * 2 * 8192];   // 64 MB
// B: per (img = kh*4+chunk, 8 imgs): [split 2][256 k][64 d] = 65536 B each
__device__ __align__(1024) __nv_bfloat16 g_Bimg[8 * 2 * 16384];        // 512 KB

// ---------------------------------------------------------------------------
// PTX helpers (portable PTX only — no 'a'-suffix features)
// ---------------------------------------------------------------------------
__device__ __forceinline__ uint32_t smem_u32(const void* p) {
    uint32_t a;
    asm("{ .reg .u64 tmp; cvta.to.shared.u64 tmp, %1; cvt.u32.u64 %0, tmp; }"
        : "=r"(a) : "l"(p));
    return a;
}

#define MBARRIER_INIT(addr, cnt) \
    asm volatile("mbarrier.init.shared.b64 [%0], %1;" :: "r"(addr), "r"(cnt) : "memory")
#define MBARRIER_EXPECT_TX(addr, bytes) \
    asm volatile("mbarrier.arrive.expect_tx.shared.b64 _, [%0], %1;" \
                 :: "r"(addr), "r"(bytes) : "memory")

#define MBARRIER_WAIT_PARITY(addr, par) do {                                   \
    uint32_t _m = (addr), _p = (par), _done;                                   \
    asm volatile("{\n\t.reg .pred p;\n\t"                                      \
        "mbarrier.try_wait.parity.acquire.cta.shared::cta.b64 p, [%1], %2;\n\t"\
        "selp.b32 %0, 1, 0, p;\n\t}"                                           \
        : "=r"(_done) : "r"(_m), "r"(_p) : "memory");                          \
    if (!_done) {                                                              \
        asm volatile("{\n\t.reg .pred P1;\n\t"                                 \
            "WL_%=:\n\t"                                                       \
            "mbarrier.try_wait.parity.acquire.cta.shared::cta.b64 P1, [%0], %1, 0x989680;\n\t" \
            "@P1 bra.uni WD_%=;\n\t"                                           \
            "bra.uni WL_%=;\n\t"                                               \
            "WD_%=:\n\t}"                                                      \
            :: "r"(_m), "r"(_p) : "memory");                                   \
    }                                                                          \
} while (0)

__device__ __forceinline__ void bulk_g2s(uint32_t dst, const void* src,
                                         uint32_t bytes, uint32_t mbar) {
    asm volatile("cp.async.bulk.shared::cta.global.mbarrier::complete_tx::bytes "
                 "[%0], [%1], %2, [%3];"
                 :: "r"(dst), "l"(src), "r"(bytes), "r"(mbar) : "memory");
}

#define LDSM_X4(r0, r1, r2, r3, a) \
    asm volatile("ldmatrix.sync.aligned.m8n8.x4.shared.b16 {%0,%1,%2,%3}, [%4];" \
        : "=r"(r0), "=r"(r1), "=r"(r2), "=r"(r3) : "r"(a))
#define LDSM_X2(r0, r1, a) \
    asm volatile("ldmatrix.sync.aligned.m8n8.x2.shared.b16 {%0,%1}, [%2];" \
        : "=r"(r0), "=r"(r1) : "r"(a))

#define MMA_BF16(d0, d1, d2, d3, a0, a1, a2, a3, b0, b1) \
    asm volatile("mma.sync.aligned.m16n8k16.row.col.f32.bf16.bf16.f32 " \
        "{%0,%1,%2,%3}, {%4,%5,%6,%7}, {%8,%9}, {%0,%1,%2,%3};" \
        : "+f"(d0), "+f"(d1), "+f"(d2), "+f"(d3) \
        : "r"(a0), "r"(a1), "r"(a2), "r"(a3), "r"(b0), "r"(b1))

__device__ __forceinline__ unsigned short bfbits(__nv_bfloat16 h) {
    return *reinterpret_cast<unsigned short*>(&h);
}

// 4-product split GEMM (hi*hi + hi*lo + lo*hi + lo*lo): noise ~2^-24
__device__ __forceinline__ void mma4(float* d, const uint32_t* ah, const uint32_t* al,
                                     const uint32_t* bh, const uint32_t* bl) {
    MMA_BF16(d[0], d[1], d[2], d[3], ah[0], ah[1], ah[2], ah[3], bh[0], bh[1]);
    MMA_BF16(d[0], d[1], d[2], d[3], ah[0], ah[1], ah[2], ah[3], bl[0], bl[1]);
    MMA_BF16(d[0], d[1], d[2], d[3], al[0], al[1], al[2], al[3], bh[0], bh[1]);
    MMA_BF16(d[0], d[1], d[2], d[3], al[0], al[1], al[2], al[3], bl[0], bl[1]);
}

// ---------------------------------------------------------------------------
// Grid barrier among the NB prep CTAs (all co-resident)
// ---------------------------------------------------------------------------
__device__ __forceinline__ void grid_barrier() {
    __syncthreads();
    if (threadIdx.x == 0) {
        __threadfence();
        unsigned t = atomicAdd(&g_bar, 1u);
        unsigned target = (t / NB + 1u) * NB;
        volatile unsigned* p = &g_bar;
        while (*p < target) { }
        __threadfence();
    }
    __syncthreads();
}

// ---------------------------------------------------------------------------
// Build a K-major bf16-split smem image from f32 rows.
//   dst: smem byte pointer; src: f32 row-major, ld = row stride (floats).
//   nrows rows x 256 cols; chunk c (64 cols) at dst + c*nrows*128,
//   lo split at +4*nrows*128. If diag_row0 != NODIAG, builds M = 2I - src.
// ---------------------------------------------------------------------------
__device__ __forceinline__ void build_img(char* dst, const float* __restrict__ src,
                                          int ld, int nrows, int diag_row0) {
    const int cstride = nrows * 128;
    const int sstride = cstride * 4;
    for (int tt = threadIdx.x; tt < nrows * 32; tt += 256) {
        const int row = tt >> 5, c0 = (tt & 31) * 8;
        float f[8];
        *(float4*)&f[0] = *(const float4*)&src[row * ld + c0];
        *(float4*)&f[4] = *(const float4*)&src[row * ld + c0 + 4];
        if (diag_row0 != NODIAG) {
            const int gr = diag_row0 + row;
#pragma unroll
            for (int j = 0; j < 8; ++j)
                f[j] = ((gr == c0 + j) ? 2.0f : 0.0f) - f[j];
        }
        unsigned uh[4], ul[4];
#pragma unroll
        for (int q = 0; q < 4; ++q) {
            __nv_bfloat16 h0 = __float2bfloat16_rn(f[2 * q]);
            __nv_bfloat16 h1 = __float2bfloat16_rn(f[2 * q + 1]);
            __nv_bfloat16 l0 = __float2bfloat16_rn(f[2 * q] - __bfloat162float(h0));
            __nv_bfloat16 l1 = __float2bfloat16_rn(f[2 * q + 1] - __bfloat162float(h1));
            uh[q] = (unsigned)bfbits(h0) | ((unsigned)bfbits(h1) << 16);
            ul[q] = (unsigned)bfbits(l0) | ((unsigned)bfbits(l1) << 16);
        }
        const int chunk = c0 >> 6, g = (c0 & 63) >> 3;
        const int off = chunk * cstride + row * 128 + ((g ^ (row & 7)) << 4);
        *(uint4*)(dst + off) = make_uint4(uh[0], uh[1], uh[2], uh[3]);
        *(uint4*)(dst + sstride + off) = make_uint4(ul[0], ul[1], ul[2], ul[3]);
    }
}

// ---------------------------------------------------------------------------
// Prep kernel, 148 CTAs x 256 threads, 98304 B dynamic smem:
//   bid <  64 : scalar gram (+Y0) -> HMMA init/dual/final NS passes -> W images
//   bid >= 64 : convert X -> bf16-split swizzled A images (concurrent)
// ---------------------------------------------------------------------------
#define SMEM_PREP 98304

__global__ __launch_bounds__(256, 1)
void prep_kernel(const float* __restrict__ dict, const float* __restrict__ X) {
    extern __shared__ __align__(1024) char pool[];
    const uint32_t pb = smem_u32(pool);
    const int bid = blockIdx.x;
    const int t = threadIdx.x;

    // =========================== Converter CTAs ============================
    if (bid >= NB) {
        float (*Sx)[132] = (float(*)[132])pool;
        for (int tile = bid - NB; tile < 2048; tile += NCONV) {
            const int nt = tile >> 2, c = tile & 3;
            const int n0 = nt * 128, d0 = c * 64;
            {
                const int dl = t >> 5, n4 = (t & 31) * 4;
#pragma unroll
                for (int j = 0; j < 8; ++j) {
                    float4 v = *(const float4*)&X[(size_t)(d0 + dl + j * 8) * NCOL + n0 + n4];
                    *(float4*)&Sx[dl + j * 8][n4] = v;
                }
            }
            __syncthreads();
            {
                const int m = t >> 1, half = t & 1;
                char* pA = (char*)g_Aimg + (size_t)tile * 32768;
#pragma unroll
                for (int gl = 0; gl < 4; ++gl) {
                    unsigned uh[4], ul[4];
#pragma unroll
                    for (int q = 0; q < 4; ++q) {
                        int i0 = gl * 8 + q * 2;
                        float v0 = Sx[half * 32 + i0][m];
                        float v1 = Sx[half * 32 + i0 + 1][m];
                        __nv_bfloat16 h0 = __float2bfloat16_rn(v0);
                        __nv_bfloat16 h1 = __float2bfloat16_rn(v1);
                        __nv_bfloat16 l0 = __float2bfloat16_rn(v0 - __bfloat162float(h0));
                        __nv_bfloat16 l1 = __float2bfloat16_rn(v1 - __bfloat162float(h1));
                        uh[q] = (unsigned)bfbits(h0) | ((unsigned)bfbits(h1) << 16);
                        ul[q] = (unsigned)bfbits(l0) | ((unsigned)bfbits(l1) << 16);
                    }
                    int g = half * 4 + gl;
                    int off = m * 128 + ((g ^ (m & 7)) << 4);
                    *(uint4*)(pA + off)         = make_uint4(uh[0], uh[1], uh[2], uh[3]);
                    *(uint4*)(pA + 16384 + off) = make_uint4(ul[0], ul[1], ul[2], ul[3]);
                }
            }
            __syncthreads();
        }
        return;
    }

    // ============================= Prep CTAs ===============================
    const int wid = t >> 5, lane = t & 31;
    const int i0 = (bid >> 3) * 32;      // output row tile base (NS passes)
    const int j0 = (bid & 7) * 32;       // output col tile base
    const int m0 = (wid & 1) * 16;       // warp sub-tile
    const int n0 = (wid >> 1) * 8;
    const int er = lane >> 2, ec = (lane & 3) * 2;
    const int ar = m0 + (lane & 15), ag = lane >> 4;
    const int br = n0 + (lane & 7), bg = (lane >> 3) & 1;

    // ---------------- Phase 1: scalar gram G = dict^T dict, Y0 = aI + bG ---
    {
        float (*As)[34] = (float(*)[34])pool;
        float (*Bs)[34] = (float(*)[34])(pool + 32 * 34 * 4);
        const int tx = t & 15, ty = t >> 4;
        const int lr = t >> 3, lc = (t & 7) * 4;
        float a00 = 0.f, a01 = 0.f, a10 = 0.f, a11 = 0.f;
        for (int kc = 0; kc < KAT; kc += 32) {
            float4 va = *(const float4*)&dict[(kc + lr) * DIMD + i0 + lc];
            float4 vb = *(const float4*)&dict[(kc + lr) * DIMD + j0 + lc];
            As[lr][lc + 0] = va.x; As[lr][lc + 1] = va.y;
            As[lr][lc + 2] = va.z; As[lr][lc + 3] = va.w;
            Bs[lr][lc + 0] = vb.x; Bs[lr][lc + 1] = vb.y;
            Bs[lr][lc + 2] = vb.z; Bs[lr][lc + 3] = vb.w;
            __syncthreads();
#pragma unroll
            for (int k = 0; k < 32; ++k) {
                float2 a = *(const float2*)&As[k][ty * 2];
                float2 b = *(const float2*)&Bs[k][tx * 2];
                a00 += a.x * b.x; a01 += a.x * b.y;
                a10 += a.y * b.x; a11 += a.y * b.y;
            }
            __syncthreads();
        }
        const int r0 = i0 + ty * 2, c0 = j0 + tx * 2;
        float acc[2][2] = {{a00, a01}, {a10, a11}};
#pragma unroll
        for (int ii = 0; ii < 2; ++ii)
#pragma unroll
            for (int jj = 0; jj < 2; ++jj) {
                float g = acc[ii][jj];
                g_G[(r0 + ii) * DIMD + c0 + jj] = g;
                float y0 = B_COEF * g;
                if (r0 + ii == c0 + jj) y0 += A_COEF;
                g_Y[(r0 + ii) * DIMD + c0 + jj] = y0;
            }
    }
    grid_barrier();

    // ---------------- Init pass: Z0 = a*G + b*(G*G)  (G symmetric) ---------
    {
        build_img(pool,         g_G + i0 * DIMD, DIMD, 32, NODIAG);   // A = G rows
        build_img(pool + 65536, g_G + j0 * DIMD, DIMD, 32, NODIAG);   // B = G rows (sym)
        __syncthreads();
        float ac[4] = {0.f, 0.f, 0.f, 0.f};
#pragma unroll
        for (int c = 0; c < 4; ++c) {
            const uint32_t Ab = pb + c * 4096, Bb = pb + 65536 + c * 4096;
#pragma unroll
            for (int ks = 0; ks < 4; ++ks) {
                uint32_t ah[4], al[4], bh[2], bl[2];
                uint32_t aad = Ab + ar * 128 + (((ks * 2 + ag) ^ (ar & 7)) << 4);
                LDSM_X4(ah[0], ah[1], ah[2], ah[3], aad);
                LDSM_X4(al[0], al[1], al[2], al[3], aad + 16384);
                uint32_t bad = Bb + br * 128 + (((ks * 2 + bg) ^ (br & 7)) << 4);
                LDSM_X2(bh[0], bh[1], bad);
                LDSM_X2(bl[0], bl[1], bad + 16384);
                mma4(ac, ah, al, bh, bl);
            }
        }
        const int r0 = i0 + m0 + er, c0 = j0 + n0 + ec;
        g_Z[r0 * DIMD + c0]           = A_COEF * g_G[r0 * DIMD + c0]           + B_COEF * ac[0];
        g_Z[r0 * DIMD + c0 + 1]       = A_COEF * g_G[r0 * DIMD + c0 + 1]       + B_COEF * ac[1];
        g_Z[(r0 + 8) * DIMD + c0]     = A_COEF * g_G[(r0 + 8) * DIMD + c0]     + B_COEF * ac[2];
        g_Z[(r0 + 8) * DIMD + c0 + 1] = A_COEF * g_G[(r0 + 8) * DIMD + c0 + 1] + B_COEF * ac[3];
    }
    grid_barrier();

    // ---------------- Dual NS passes: Y' = Y*M, Z' = Z*M,  M = 2I - Z ------
    int p = 0;
    for (int it = 0; it < NDUAL; ++it) {
        const float* Yp = g_Y + p * DIMD * DIMD;
        const float* Zp = g_Z + p * DIMD * DIMD;
        build_img(pool,         Yp + i0 * DIMD, DIMD, 32, NODIAG);  // A1 = Y rows
        build_img(pool + 32768, Zp + i0 * DIMD, DIMD, 32, NODIAG);  // A2 = Z rows
        build_img(pool + 65536, Zp + j0 * DIMD, DIMD, 32, j0);      // B = M rows (sym)
        __syncthreads();
        float aY[4] = {0.f, 0.f, 0.f, 0.f};
        float aZ[4] = {0.f, 0.f, 0.f, 0.f};
#pragma unroll
        for (int c = 0; c < 4; ++c) {
            const uint32_t A1 = pb + c * 4096;
            const uint32_t A2 = pb + 32768 + c * 4096;
            const uint32_t Bb = pb + 65536 + c * 4096;
#pragma unroll
            for (int ks = 0; ks < 4; ++ks) {
                uint32_t ah[4], al[4], zh[4], zl[4], bh[2], bl[2];
                const uint32_t aoff = ar * 128 + (((ks * 2 + ag) ^ (ar & 7)) << 4);
                LDSM_X4(ah[0], ah[1], ah[2], ah[3], A1 + aoff);
                LDSM_X4(al[0], al[1], al[2], al[3], A1 + aoff + 16384);
                LDSM_X4(zh[0], zh[1], zh[2], zh[3], A2 + aoff);
                LDSM_X4(zl[0], zl[1], zl[2], zl[3], A2 + aoff + 16384);
                uint32_t bad = Bb + br * 128 + (((ks * 2 + bg) ^ (br & 7)) << 4);
                LDSM_X2(bh[0], bh[1], bad);
                LDSM_X2(bl[0], bl[1], bad + 16384);
                mma4(aY, ah, al, bh, bl);
                mma4(aZ, zh, zl, bh, bl);
            }
        }
        float* Yn = g_Y + (p ^ 1) * DIMD * DIMD;
        float* Zn = g_Z + (p ^ 1) * DIMD * DIMD;
        const int r0 = i0 + m0 + er, c0 = j0 + n0 + ec;
        Yn[r0 * DIMD + c0] = aY[0];           Yn[r0 * DIMD + c0 + 1] = aY[1];
        Yn[(r0 + 8) * DIMD + c0] = aY[2];     Yn[(r0 + 8) * DIMD + c0 + 1] = aY[3];
        Zn[r0 * DIMD + c0] = aZ[0];           Zn[r0 * DIMD + c0 + 1] = aZ[1];
        Zn[(r0 + 8) * DIMD + c0] = aZ[2];     Zn[(r0 + 8) * DIMD + c0 + 1] = aZ[3];
        grid_barrier();
        p ^= 1;
    }

    // ---------------- Final pass: Yf = Y*(2I - Z) --------------------------
    {
        const float* Yp = g_Y + p * DIMD * DIMD;
        const float* Zp = g_Z + p * DIMD * DIMD;
        build_img(pool,         Yp + i0 * DIMD, DIMD, 32, NODIAG);
        build_img(pool + 65536, Zp + j0 * DIMD, DIMD, 32, j0);
        __syncthreads();
        float ac[4] = {0.f, 0.f, 0.f, 0.f};
#pragma unroll
        for (int c = 0; c < 4; ++c) {
            const uint32_t Ab = pb + c * 4096, Bb = pb + 65536 + c * 4096;
#pragma unroll
            for (int ks = 0; ks < 4; ++ks) {
                uint32_t ah[4], al[4], bh[2], bl[2];
                uint32_t aad = Ab + ar * 128 + (((ks * 2 + ag) ^ (ar & 7)) << 4);
                LDSM_X4(ah[0], ah[1], ah[2], ah[3], aad);
                LDSM_X4(al[0], al[1], al[2], al[3], aad + 16384);
                uint32_t bad = Bb + br * 128 + (((ks * 2 + bg) ^ (br & 7)) << 4);
                LDSM_X2(bh[0], bh[1], bad);
                LDSM_X2(bl[0], bl[1], bad + 16384);
                mma4(ac, ah, al, bh, bl);
            }
        }
        float* Yn = g_Y + (p ^ 1) * DIMD * DIMD;
        const int r0 = i0 + m0 + er, c0 = j0 + n0 + ec;
        Yn[r0 * DIMD + c0] = ac[0];           Yn[r0 * DIMD + c0 + 1] = ac[1];
        Yn[(r0 + 8) * DIMD + c0] = ac[2];     Yn[(r0 + 8) * DIMD + c0 + 1] = ac[3];
    }
    grid_barrier();
    p ^= 1;

    // ---------------- W pass: C[kat][dh] = sum_e dict[kat][e]*Yf[dh][e] ----
    // Output 32 kat x 64 dh per CTA, written straight into g_Bimg (split+swizzled).
    {
        const float* Yf = g_Y + p * DIMD * DIMD;
        const int kt = bid >> 2, dbase = (bid & 3) * 64;
        build_img(pool,         dict + (size_t)kt * 32 * DIMD, DIMD, 32, NODIAG); // A = dict rows
        build_img(pool + 32768, Yf + dbase * DIMD, DIMD, 64, NODIAG);             // B = Yf rows
        __syncthreads();
        const int nb0 = (wid >> 1) * 16;
        float aw[2][4] = {{0.f, 0.f, 0.f, 0.f}, {0.f, 0.f, 0.f, 0.f}};
#pragma unroll
        for (int c = 0; c < 4; ++c) {
            const uint32_t Ab = pb + c * 4096;
            const uint32_t Bb = pb + 32768 + c * 8192;
#pragma unroll
            for (int ks = 0; ks < 4; ++ks) {
                uint32_t ah[4], al[4];
                uint32_t aad = Ab + ar * 128 + (((ks * 2 + ag) ^ (ar & 7)) << 4);
                LDSM_X4(ah[0], ah[1], ah[2], ah[3], aad);
                LDSM_X4(al[0], al[1], al[2], al[3], aad + 16384);
#pragma unroll
                for (int nf = 0; nf < 2; ++nf) {
                    const int brw = nb0 + nf * 8 + (lane & 7);
                    uint32_t bh[2], bl[2];
                    uint32_t bad = Bb + brw * 128 + (((ks * 2 + bg) ^ (brw & 7)) << 4);
                    LDSM_X2(bh[0], bh[1], bad);
                    LDSM_X2(bl[0], bl[1], bad + 32768);
                    mma4(aw[nf], ah, al, bh, bl);
                }
            }
        }
        // Epilogue: write bf16-split swizzled g_Bimg
#pragma unroll
        for (int nf = 0; nf < 2; ++nf) {
#pragma unroll
            for (int h = 0; h < 2; ++h) {
                float v0 = aw[nf][h * 2 + 0], v1 = aw[nf][h * 2 + 1];
                const int m = m0 + er + h * 8;            // kat-local 0..31
                const int kat = kt * 32 + m;
                const int n = nb0 + nf * 8 + ec;          // dh-local 0..63
                const int kh = kat >> 8;
                const size_t imgbyte = (size_t)(kh * 4 + (bid & 3)) * 65536;
                const int row = kat & 255;
                const int off = row * 128 + (((n >> 3) ^ (row & 7)) << 4) + (n & 7) * 2;
                __nv_bfloat16 h0 = __float2bfloat16_rn(v0);
                __nv_bfloat16 h1 = __float2bfloat16_rn(v1);
                __nv_bfloat16 l0 = __float2bfloat16_rn(v0 - __bfloat162float(h0));
                __nv_bfloat16 l1 = __float2bfloat16_rn(v1 - __bfloat162float(h1));
                *(uint32_t*)((char*)g_Bimg + imgbyte + off) =
                    (unsigned)bfbits(h0) | ((unsigned)bfbits(h1) << 16);
                *(uint32_t*)((char*)g_Bimg + imgbyte + 32768 + off) =
                    (unsigned)bfbits(l0) | ((unsigned)bfbits(l1) << 16);
            }
        }
    }
}

// ---------------------------------------------------------------------------
// Persistent tensor-core GEMM: out[n][k] = sum_d X[d][n] W[d][k]
// 148 CTAs x 512 threads (16 warps, warp tile 32n x 32k = wn4 x wk4).
// Each CTA streams its (nt,kq) items through a 3-stage cp.async.bulk pipeline.
// Stage buffer (65536 B): Ahi +0, Alo +16K, Bhi +32K, Blo +48K.
// ---------------------------------------------------------------------------
#define SMEM_MMA (1024 + 3 * 65536)

__global__ __launch_bounds__(512, 1)
void out_mma_kernel(float* __restrict__ out) {
    extern __shared__ __align__(1024) char smem[];
    const uint32_t sb = smem_u32(smem);
    const uint32_t BUF0 = sb + 1024;

    const int bid = blockIdx.x;
    const int t = threadIdx.x, wid = t >> 5, lane = t & 31;
    const int wn = wid & 3;          // n quarter (32 rows)
    const int wk = wid >> 2;         // k quarter (32 cols)

    if (t == 0) {
        MBARRIER_INIT(sb + 0, 1); MBARRIER_INIT(sb + 16, 1); MBARRIER_INIT(sb + 32, 1);
    }
    __syncthreads();

    const int nitems = (2047 - bid) / 148 + 1;
    const int nc = nitems * 4;

    auto fill = [&](int cc) {
        const int item = bid + (cc >> 2) * 148;
        const int c = cc & 3;
        const int nt = item >> 2, kq = item & 3;
        const uint32_t buf = BUF0 + (uint32_t)(cc % 3) * 65536;
        const uint32_t mb = sb + (uint32_t)(cc % 3) * 16;
        MBARRIER_EXPECT_TX(mb, 65536u);
        bulk_g2s(buf, (const char*)g_Aimg + (size_t)nt * 131072 + (size_t)c * 32768,
                 32768u, mb);
        const char* Bb = (const char*)g_Bimg + (size_t)(kq >> 1) * 262144
                       + (size_t)c * 65536 + (size_t)(kq & 1) * 16384;
        bulk_g2s(buf + 32768, Bb, 16384u, mb);
        bulk_g2s(buf + 49152, Bb + 32768, 16384u, mb);
    };
    if (t == 0) {
        fill(0);
        if (nc > 1) fill(1);
        if (nc > 2) fill(2);
    }

    const int a_row = lane & 15, a_gsel = lane >> 4;
    const int b_row = lane & 7, b_gsel = (lane >> 3) & 1;

    float acc[2][4][4];

    for (int cc = 0; cc < nc; ++cc) {
        const int c = cc & 3;
        if (c == 0) {
#pragma unroll
            for (int mf = 0; mf < 2; ++mf)
#pragma unroll
                for (int nf = 0; nf < 4; ++nf)
#pragma unroll
                    for (int q = 0; q < 4; ++q) acc[mf][nf][q] = 0.f;
        }
        MBARRIER_WAIT_PARITY(sb + (uint32_t)(cc % 3) * 16, (cc / 3) & 1);
        const uint32_t buf = BUF0 + (uint32_t)(cc % 3) * 65536;
        const uint32_t Ahi = buf, Alo = buf + 16384;
        const uint32_t Bhi = buf + 32768, Blo = buf + 49152;

#pragma unroll
        for (int ks = 0; ks < 4; ++ks) {
            const int g = ks * 2;
            uint32_t ah[2][4], al[2][4], bh[4][2], bl[4][2];
#pragma unroll
            for (int mf = 0; mf < 2; ++mf) {
                const int row = wn * 32 + mf * 16 + a_row;
                const uint32_t aoff = row * 128 + (((g + a_gsel) ^ (row & 7)) << 4);
                LDSM_X4(ah[mf][0], ah[mf][1], ah[mf][2], ah[mf][3], Ahi + aoff);
                LDSM_X4(al[mf][0], al[mf][1], al[mf][2], al[mf][3], Alo + aoff);
            }
#pragma unroll
            for (int nf = 0; nf < 4; ++nf) {
                const int row = wk * 32 + nf * 8 + b_row;
                const uint32_t boff = row * 128 + (((g + b_gsel) ^ (row & 7)) << 4);
                LDSM_X2(bh[nf][0], bh[nf][1], Bhi + boff);
                LDSM_X2(bl[nf][0], bl[nf][1], Blo + boff);
            }
#pragma unroll
            for (int mf = 0; mf < 2; ++mf)
#pragma unroll
                for (int nf = 0; nf < 4; ++nf) {
                    float* d = acc[mf][nf];
                    MMA_BF16(d[0], d[1], d[2], d[3],
                             ah[mf][0], ah[mf][1], ah[mf][2], ah[mf][3],
                             bh[nf][0], bh[nf][1]);
                    MMA_BF16(d[0], d[1], d[2], d[3],
                             ah[mf][0], ah[mf][1], ah[mf][2], ah[mf][3],
                             bl[nf][0], bl[nf][1]);
                    MMA_BF16(d[0], d[1], d[2], d[3],
                             al[mf][0], al[mf][1], al[mf][2], al[mf][3],
                             bh[nf][0], bh[nf][1]);
                }
        }
        __syncthreads();                 // all warps done with this stage
        if (t == 0 && cc + 3 < nc) fill(cc + 3);

        if (c == 3) {                    // epilogue for this item
            const int item = bid + (cc >> 2) * 148;
            const int nt = item >> 2, kq = item & 3;
            const int er = lane >> 2, ec = (lane & 3) * 2;
            const size_t nbase = (size_t)nt * 128 + wn * 32 + er;
            const int kbase = kq * 128 + wk * 32 + ec;
#pragma unroll
            for (int mf = 0; mf < 2; ++mf) {
                const size_t r0 = nbase + mf * 16;
#pragma unroll
                for (int nf = 0; nf < 4; ++nf) {
                    const int col = kbase + nf * 8;
                    float* d = acc[mf][nf];
                    *(float2*)&out[r0 * KAT + col]       = make_float2(d[0], d[1]);
                    *(float2*)&out[(r0 + 8) * KAT + col] = make_float2(d[2], d[3]);
                }
            }
        }
    }
}

// ---------------------------------------------------------------------------
// Launch: 2 graph nodes, no allocations, deterministic, replay-safe.
// ---------------------------------------------------------------------------
extern "C" void kernel_launch(void* const* d_in, const int* in_sizes, int n_in,
                              void* d_out, int out_size) {
    (void)in_sizes; (void)n_in; (void)out_size;
    const float* z_e  = (const float*)d_in[0];   // [DIMD, NCOL]
    const float* dict = (const float*)d_in[1];   // [KAT, DIMD]
    float* out = (float*)d_out;                  // [NCOL, KAT]

    cudaFuncSetAttribute(prep_kernel,
                         cudaFuncAttributeMaxDynamicSharedMemorySize, SMEM_PREP);
    cudaFuncSetAttribute(out_mma_kernel,
                         cudaFuncAttributeMaxDynamicSharedMemorySize, SMEM_MMA);

    // 1) gram + HMMA Newton-Schulz (4-product) + W images, concurrent with
    //    X image convert on the other 84 SMs
    prep_kernel<<<NB + NCONV, 256, SMEM_PREP>>>(dict, z_e);

    // 2) persistent tensor-core GEMM: out = X^T W (bf16 2-split, 3 products)
    out_mma_kernel<<<148, 512, SMEM_MMA>>>(out);
}

// round 11
// speedup vs baseline: 1.1054x; 1.1054x over previous
#include <cuda_runtime.h>
#include <cuda_fp16.h>
#include <cstdint>

// Problem constants
#define DIMD 256
#define KAT  512
#define NCOL 65536
#define NB   64          // prep CTAs (barrier group)
#define NCONV 84         // converter CTAs (NB+NCONV = 148 SMs, all co-resident)
#define NDUAL 6          // dual Newton-Schulz passes (then one final Y-only pass)

// Chebyshev degree-1 start for Newton-Schulz (residual 0.865 on [30,1600])
#define A_COEF 4.57720e-3f
#define B_COEF (-2.80809e-6f)
#define NODIAG (-1000000)

// ---------------------------------------------------------------------------
// Device scratch (no allocations allowed)
// ---------------------------------------------------------------------------
__device__ float g_G[DIMD * DIMD];
__device__ float g_Y[2 * DIMD * DIMD];    // Y ping-pong
__device__ float g_Z[2 * DIMD * DIMD];    // Z = G*Y ping-pong
__device__ unsigned g_bar = 0;            // monotone grid barrier

// Pre-swizzled fp16-split images (XOR swizzle within 128B rows):
// A: per (ntile 0..511, dchunk 0..3): [split 2][128 n][64 d] = 32768 B each
__device__ __align__(1024) __half g_Aimg[512 * 4 * 2 * 8192];   // 64 MB
// B: per (img = kh*4+chunk, 8 imgs): [split 2][256 k][64 d] = 65536 B each
__device__ __align__(1024) __half g_Bimg[8 * 2 * 16384];        // 512 KB

// ---------------------------------------------------------------------------
// PTX helpers (portable PTX only — no 'a'-suffix features)
// ---------------------------------------------------------------------------
__device__ __forceinline__ uint32_t smem_u32(const void* p) {
    uint32_t a;
    asm("{ .reg .u64 tmp; cvta.to.shared.u64 tmp, %1; cvt.u32.u64 %0, tmp; }"
        : "=r"(a) : "l"(p));
    return a;
}

#define MBARRIER_INIT(addr, cnt) \
    asm volatile("mbarrier.init.shared.b64 [%0], %1;" :: "r"(addr), "r"(cnt) : "memory")
#define MBARRIER_EXPECT_TX(addr, bytes) \
    asm volatile("mbarrier.arrive.expect_tx.shared.b64 _, [%0], %1;" \
                 :: "r"(addr), "r"(bytes) : "memory")
#define MBARRIER_ARRIVE(addr) \
    asm volatile("mbarrier.arrive.shared.b64 _, [%0];" :: "r"(addr) : "memory")

#define MBARRIER_WAIT_PARITY(addr, par) do {                                   \
    uint32_t _m = (addr), _p = (par), _done;                                   \
    asm volatile("{\n\t.reg .pred p;\n\t"                                      \
        "mbarrier.try_wait.parity.acquire.cta.shared::cta.b64 p, [%1], %2;\n\t"\
        "selp.b32 %0, 1, 0, p;\n\t}"                                           \
        : "=r"(_done) : "r"(_m), "r"(_p) : "memory");                          \
    if (!_done) {                                                              \
        asm volatile("{\n\t.reg .pred P1;\n\t"                                 \
            "WL_%=:\n\t"                                                       \
            "mbarrier.try_wait.parity.acquire.cta.shared::cta.b64 P1, [%0], %1, 0x989680;\n\t" \
            "@P1 bra.uni WD_%=;\n\t"                                           \
            "bra.uni WL_%=;\n\t"                                               \
            "WD_%=:\n\t}"                                                      \
            :: "r"(_m), "r"(_p) : "memory");                                   \
    }                                                                          \
} while (0)

__device__ __forceinline__ void bulk_g2s(uint32_t dst, const void* src,
                                         uint32_t bytes, uint32_t mbar) {
    asm volatile("cp.async.bulk.shared::cta.global.mbarrier::complete_tx::bytes "
                 "[%0], [%1], %2, [%3];"
                 :: "r"(dst), "l"(src), "r"(bytes), "r"(mbar) : "memory");
}

#define LDSM_X4(r0, r1, r2, r3, a) \
    asm volatile("ldmatrix.sync.aligned.m8n8.x4.shared.b16 {%0,%1,%2,%3}, [%4];" \
        : "=r"(r0), "=r"(r1), "=r"(r2), "=r"(r3) : "r"(a))
#define LDSM_X2(r0, r1, a) \
    asm volatile("ldmatrix.sync.aligned.m8n8.x2.shared.b16 {%0,%1}, [%2];" \
        : "=r"(r0), "=r"(r1) : "r"(a))

#define MMA_F16(d0, d1, d2, d3, a0, a1, a2, a3, b0, b1) \
    asm volatile("mma.sync.aligned.m16n8k16.row.col.f32.f16.f16.f32 " \
        "{%0,%1,%2,%3}, {%4,%5,%6,%7}, {%8,%9}, {%0,%1,%2,%3};" \
        : "+f"(d0), "+f"(d1), "+f"(d2), "+f"(d3) \
        : "r"(a0), "r"(a1), "r"(a2), "r"(a3), "r"(b0), "r"(b1))

__device__ __forceinline__ unsigned short hbits(__half h) {
    return *reinterpret_cast<unsigned short*>(&h);
}

// pack two floats into one fp16x2 hi word + one fp16x2 lo word helper
__device__ __forceinline__ void split2(float v0, float v1, unsigned& uh, unsigned& ul) {
    __half h0 = __float2half_rn(v0);
    __half h1 = __float2half_rn(v1);
    __half l0 = __float2half_rn(v0 - __half2float(h0));
    __half l1 = __float2half_rn(v1 - __half2float(h1));
    uh = (unsigned)hbits(h0) | ((unsigned)hbits(h1) << 16);
    ul = (unsigned)hbits(l0) | ((unsigned)hbits(l1) << 16);
}

// 4-product split GEMM (hi*hi + hi*lo + lo*hi + lo*lo)
__device__ __forceinline__ void mma4(float* d, const uint32_t* ah, const uint32_t* al,
                                     const uint32_t* bh, const uint32_t* bl) {
    MMA_F16(d[0], d[1], d[2], d[3], ah[0], ah[1], ah[2], ah[3], bh[0], bh[1]);
    MMA_F16(d[0], d[1], d[2], d[3], ah[0], ah[1], ah[2], ah[3], bl[0], bl[1]);
    MMA_F16(d[0], d[1], d[2], d[3], al[0], al[1], al[2], al[3], bh[0], bh[1]);
    MMA_F16(d[0], d[1], d[2], d[3], al[0], al[1], al[2], al[3], bl[0], bl[1]);
}

// ---------------------------------------------------------------------------
// Grid barrier among the NB prep CTAs (all co-resident)
// ---------------------------------------------------------------------------
__device__ __forceinline__ void grid_barrier() {
    __syncthreads();
    if (threadIdx.x == 0) {
        __threadfence();
        unsigned t = atomicAdd(&g_bar, 1u);
        unsigned target = (t / NB + 1u) * NB;
        volatile unsigned* p = &g_bar;
        while (*p < target) { }
        __threadfence();
    }
    __syncthreads();
}

// ---------------------------------------------------------------------------
// Build a K-major fp16-split smem image from f32 rows.
//   dst: smem byte pointer; src: f32 row-major, ld = row stride (floats).
//   nrows rows x 256 cols; chunk c (64 cols) at dst + c*nrows*128,
//   lo split at +4*nrows*128. If diag_row0 != NODIAG, builds M = 2I - src.
// ---------------------------------------------------------------------------
__device__ __forceinline__ void build_img(char* dst, const float* __restrict__ src,
                                          int ld, int nrows, int diag_row0) {
    const int cstride = nrows * 128;
    const int sstride = cstride * 4;
    for (int tt = threadIdx.x; tt < nrows * 32; tt += 256) {
        const int row = tt >> 5, c0 = (tt & 31) * 8;
        float f[8];
        *(float4*)&f[0] = *(const float4*)&src[row * ld + c0];
        *(float4*)&f[4] = *(const float4*)&src[row * ld + c0 + 4];
        if (diag_row0 != NODIAG) {
            const int gr = diag_row0 + row;
#pragma unroll
            for (int j = 0; j < 8; ++j)
                f[j] = ((gr == c0 + j) ? 2.0f : 0.0f) - f[j];
        }
        unsigned uh[4], ul[4];
#pragma unroll
        for (int q = 0; q < 4; ++q)
            split2(f[2 * q], f[2 * q + 1], uh[q], ul[q]);
        const int chunk = c0 >> 6, g = (c0 & 63) >> 3;
        const int off = chunk * cstride + row * 128 + ((g ^ (row & 7)) << 4);
        *(uint4*)(dst + off) = make_uint4(uh[0], uh[1], uh[2], uh[3]);
        *(uint4*)(dst + sstride + off) = make_uint4(ul[0], ul[1], ul[2], ul[3]);
    }
}

// ---------------------------------------------------------------------------
// Prep kernel, 148 CTAs x 256 threads, 98304 B dynamic smem:
//   bid <  64 : scalar gram (+Y0) -> HMMA init/dual/final NS passes -> W images
//   bid >= 64 : convert X -> fp16-split swizzled A images (concurrent)
// ---------------------------------------------------------------------------
#define SMEM_PREP 98304

__global__ __launch_bounds__(256, 1)
void prep_kernel(const float* __restrict__ dict, const float* __restrict__ X) {
    extern __shared__ __align__(1024) char pool[];
    const uint32_t pb = smem_u32(pool);
    const int bid = blockIdx.x;
    const int t = threadIdx.x;

    // =========================== Converter CTAs ============================
    if (bid >= NB) {
        float (*Sx)[132] = (float(*)[132])pool;
        for (int tile = bid - NB; tile < 2048; tile += NCONV) {
            const int nt = tile >> 2, c = tile & 3;
            const int n0 = tile >> 2 ? nt * 128 : 0;
            const int nn0 = nt * 128, d0 = c * 64;
            (void)n0;
            {
                const int dl = t >> 5, n4 = (t & 31) * 4;
#pragma unroll
                for (int j = 0; j < 8; ++j) {
                    float4 v = *(const float4*)&X[(size_t)(d0 + dl + j * 8) * NCOL + nn0 + n4];
                    *(float4*)&Sx[dl + j * 8][n4] = v;
                }
            }
            __syncthreads();
            {
                const int m = t >> 1, half = t & 1;
                char* pA = (char*)g_Aimg + (size_t)tile * 32768;
#pragma unroll
                for (int gl = 0; gl < 4; ++gl) {
                    unsigned uh[4], ul[4];
#pragma unroll
                    for (int q = 0; q < 4; ++q) {
                        int i0 = gl * 8 + q * 2;
                        split2(Sx[half * 32 + i0][m], Sx[half * 32 + i0 + 1][m],
                               uh[q], ul[q]);
                    }
                    int g = half * 4 + gl;
                    int off = m * 128 + ((g ^ (m & 7)) << 4);
                    *(uint4*)(pA + off)         = make_uint4(uh[0], uh[1], uh[2], uh[3]);
                    *(uint4*)(pA + 16384 + off) = make_uint4(ul[0], ul[1], ul[2], ul[3]);
                }
            }
            __syncthreads();
        }
        return;
    }

    // ============================= Prep CTAs ===============================
    const int wid = t >> 5, lane = t & 31;
    const int i0 = (bid >> 3) * 32;      // output row tile base (NS passes)
    const int j0 = (bid & 7) * 32;       // output col tile base
    const int m0 = (wid & 1) * 16;       // warp sub-tile
    const int n0 = (wid >> 1) * 8;
    const int er = lane >> 2, ec = (lane & 3) * 2;
    const int ar = m0 + (lane & 15), ag = lane >> 4;
    const int br = n0 + (lane & 7), bg = (lane >> 3) & 1;

    // ---------------- Phase 1: scalar gram G = dict^T dict, Y0 = aI + bG ---
    {
        float (*As)[34] = (float(*)[34])pool;
        float (*Bs)[34] = (float(*)[34])(pool + 32 * 34 * 4);
        const int tx = t & 15, ty = t >> 4;
        const int lr = t >> 3, lc = (t & 7) * 4;
        float a00 = 0.f, a01 = 0.f, a10 = 0.f, a11 = 0.f;
        for (int kc = 0; kc < KAT; kc += 32) {
            float4 va = *(const float4*)&dict[(kc + lr) * DIMD + i0 + lc];
            float4 vb = *(const float4*)&dict[(kc + lr) * DIMD + j0 + lc];
            As[lr][lc + 0] = va.x; As[lr][lc + 1] = va.y;
            As[lr][lc + 2] = va.z; As[lr][lc + 3] = va.w;
            Bs[lr][lc + 0] = vb.x; Bs[lr][lc + 1] = vb.y;
            Bs[lr][lc + 2] = vb.z; Bs[lr][lc + 3] = vb.w;
            __syncthreads();
#pragma unroll
            for (int k = 0; k < 32; ++k) {
                float2 a = *(const float2*)&As[k][ty * 2];
                float2 b = *(const float2*)&Bs[k][tx * 2];
                a00 += a.x * b.x; a01 += a.x * b.y;
                a10 += a.y * b.x; a11 += a.y * b.y;
            }
            __syncthreads();
        }
        const int r0 = i0 + ty * 2, c0 = j0 + tx * 2;
        float acc[2][2] = {{a00, a01}, {a10, a11}};
#pragma unroll
        for (int ii = 0; ii < 2; ++ii)
#pragma unroll
            for (int jj = 0; jj < 2; ++jj) {
                float g = acc[ii][jj];
                g_G[(r0 + ii) * DIMD + c0 + jj] = g;
                float y0 = B_COEF * g;
                if (r0 + ii == c0 + jj) y0 += A_COEF;
                g_Y[(r0 + ii) * DIMD + c0 + jj] = y0;
            }
    }
    grid_barrier();

    // ---------------- Init pass: Z0 = a*G + b*(G*G)  (G symmetric) ---------
    {
        build_img(pool,         g_G + i0 * DIMD, DIMD, 32, NODIAG);   // A = G rows
        build_img(pool + 65536, g_G + j0 * DIMD, DIMD, 32, NODIAG);   // B = G rows (sym)
        __syncthreads();
        float ac[4] = {0.f, 0.f, 0.f, 0.f};
#pragma unroll
        for (int c = 0; c < 4; ++c) {
            const uint32_t Ab = pb + c * 4096, Bb = pb + 65536 + c * 4096;
#pragma unroll
            for (int ks = 0; ks < 4; ++ks) {
                uint32_t ah[4], al[4], bh[2], bl[2];
                uint32_t aad = Ab + ar * 128 + (((ks * 2 + ag) ^ (ar & 7)) << 4);
                LDSM_X4(ah[0], ah[1], ah[2], ah[3], aad);
                LDSM_X4(al[0], al[1], al[2], al[3], aad + 16384);
                uint32_t bad = Bb + br * 128 + (((ks * 2 + bg) ^ (br & 7)) << 4);
                LDSM_X2(bh[0], bh[1], bad);
                LDSM_X2(bl[0], bl[1], bad + 16384);
                mma4(ac, ah, al, bh, bl);
            }
        }
        const int r0 = i0 + m0 + er, c0 = j0 + n0 + ec;
        g_Z[r0 * DIMD + c0]           = A_COEF * g_G[r0 * DIMD + c0]           + B_COEF * ac[0];
        g_Z[r0 * DIMD + c0 + 1]       = A_COEF * g_G[r0 * DIMD + c0 + 1]       + B_COEF * ac[1];
        g_Z[(r0 + 8) * DIMD + c0]     = A_COEF * g_G[(r0 + 8) * DIMD + c0]     + B_COEF * ac[2];
        g_Z[(r0 + 8) * DIMD + c0 + 1] = A_COEF * g_G[(r0 + 8) * DIMD + c0 + 1] + B_COEF * ac[3];
    }
    grid_barrier();

    // ---------------- Dual NS passes: Y' = Y*M, Z' = Z*M,  M = 2I - Z ------
    int p = 0;
    for (int it = 0; it < NDUAL; ++it) {
        const float* Yp = g_Y + p * DIMD * DIMD;
        const float* Zp = g_Z + p * DIMD * DIMD;
        build_img(pool,         Yp + i0 * DIMD, DIMD, 32, NODIAG);  // A1 = Y rows
        build_img(pool + 32768, Zp + i0 * DIMD, DIMD, 32, NODIAG);  // A2 = Z rows
        build_img(pool + 65536, Zp + j0 * DIMD, DIMD, 32, j0);      // B = M rows (sym)
        __syncthreads();
        float aY[4] = {0.f, 0.f, 0.f, 0.f};
        float aZ[4] = {0.f, 0.f, 0.f, 0.f};
#pragma unroll
        for (int c = 0; c < 4; ++c) {
            const uint32_t A1 = pb + c * 4096;
            const uint32_t A2 = pb + 32768 + c * 4096;
            const uint32_t Bb = pb + 65536 + c * 4096;
#pragma unroll
            for (int ks = 0; ks < 4; ++ks) {
                uint32_t ah[4], al[4], zh[4], zl[4], bh[2], bl[2];
                const uint32_t aoff = ar * 128 + (((ks * 2 + ag) ^ (ar & 7)) << 4);
                LDSM_X4(ah[0], ah[1], ah[2], ah[3], A1 + aoff);
                LDSM_X4(al[0], al[1], al[2], al[3], A1 + aoff + 16384);
                LDSM_X4(zh[0], zh[1], zh[2], zh[3], A2 + aoff);
                LDSM_X4(zl[0], zl[1], zl[2], zl[3], A2 + aoff + 16384);
                uint32_t bad = Bb + br * 128 + (((ks * 2 + bg) ^ (br & 7)) << 4);
                LDSM_X2(bh[0], bh[1], bad);
                LDSM_X2(bl[0], bl[1], bad + 16384);
                mma4(aY, ah, al, bh, bl);
                mma4(aZ, zh, zl, bh, bl);
            }
        }
        float* Yn = g_Y + (p ^ 1) * DIMD * DIMD;
        float* Zn = g_Z + (p ^ 1) * DIMD * DIMD;
        const int r0 = i0 + m0 + er, c0 = j0 + n0 + ec;
        Yn[r0 * DIMD + c0] = aY[0];           Yn[r0 * DIMD + c0 + 1] = aY[1];
        Yn[(r0 + 8) * DIMD + c0] = aY[2];     Yn[(r0 + 8) * DIMD + c0 + 1] = aY[3];
        Zn[r0 * DIMD + c0] = aZ[0];           Zn[r0 * DIMD + c0 + 1] = aZ[1];
        Zn[(r0 + 8) * DIMD + c0] = aZ[2];     Zn[(r0 + 8) * DIMD + c0 + 1] = aZ[3];
        grid_barrier();
        p ^= 1;
    }

    // ---------------- Final pass: Yf = Y*(2I - Z) --------------------------
    {
        const float* Yp = g_Y + p * DIMD * DIMD;
        const float* Zp = g_Z + p * DIMD * DIMD;
        build_img(pool,         Yp + i0 * DIMD, DIMD, 32, NODIAG);
        build_img(pool + 65536, Zp + j0 * DIMD, DIMD, 32, j0);
        __syncthreads();
        float ac[4] = {0.f, 0.f, 0.f, 0.f};
#pragma unroll
        for (int c = 0; c < 4; ++c) {
            const uint32_t Ab = pb + c * 4096, Bb = pb + 65536 + c * 4096;
#pragma unroll
            for (int ks = 0; ks < 4; ++ks) {
                uint32_t ah[4], al[4], bh[2], bl[2];
                uint32_t aad = Ab + ar * 128 + (((ks * 2 + ag) ^ (ar & 7)) << 4);
                LDSM_X4(ah[0], ah[1], ah[2], ah[3], aad);
                LDSM_X4(al[0], al[1], al[2], al[3], aad + 16384);
                uint32_t bad = Bb + br * 128 + (((ks * 2 + bg) ^ (br & 7)) << 4);
                LDSM_X2(bh[0], bh[1], bad);
                LDSM_X2(bl[0], bl[1], bad + 16384);
                mma4(ac, ah, al, bh, bl);
            }
        }
        float* Yn = g_Y + (p ^ 1) * DIMD * DIMD;
        const int r0 = i0 + m0 + er, c0 = j0 + n0 + ec;
        Yn[r0 * DIMD + c0] = ac[0];           Yn[r0 * DIMD + c0 + 1] = ac[1];
        Yn[(r0 + 8) * DIMD + c0] = ac[2];     Yn[(r0 + 8) * DIMD + c0 + 1] = ac[3];
    }
    grid_barrier();
    p ^= 1;

    // ---------------- W pass: C[kat][dh] = sum_e dict[kat][e]*Yf[dh][e] ----
    // Output 32 kat x 64 dh per CTA, written straight into g_Bimg (split+swizzled).
    {
        const float* Yf = g_Y + p * DIMD * DIMD;
        const int kt = bid >> 2, dbase = (bid & 3) * 64;
        build_img(pool,         dict + (size_t)kt * 32 * DIMD, DIMD, 32, NODIAG); // A = dict rows
        build_img(pool + 32768, Yf + dbase * DIMD, DIMD, 64, NODIAG);             // B = Yf rows
        __syncthreads();
        const int nb0 = (wid >> 1) * 16;
        float aw[2][4] = {{0.f, 0.f, 0.f, 0.f}, {0.f, 0.f, 0.f, 0.f}};
#pragma unroll
        for (int c = 0; c < 4; ++c) {
            const uint32_t Ab = pb + c * 4096;
            const uint32_t Bb = pb + 32768 + c * 8192;
#pragma unroll
            for (int ks = 0; ks < 4; ++ks) {
                uint32_t ah[4], al[4];
                uint32_t aad = Ab + ar * 128 + (((ks * 2 + ag) ^ (ar & 7)) << 4);
                LDSM_X4(ah[0], ah[1], ah[2], ah[3], aad);
                LDSM_X4(al[0], al[1], al[2], al[3], aad + 16384);
#pragma unroll
                for (int nf = 0; nf < 2; ++nf) {
                    const int brw = nb0 + nf * 8 + (lane & 7);
                    uint32_t bh[2], bl[2];
                    uint32_t bad = Bb + brw * 128 + (((ks * 2 + bg) ^ (brw & 7)) << 4);
                    LDSM_X2(bh[0], bh[1], bad);
                    LDSM_X2(bl[0], bl[1], bad + 32768);
                    mma4(aw[nf], ah, al, bh, bl);
                }
            }
        }
        // Epilogue: write fp16-split swizzled g_Bimg
#pragma unroll
        for (int nf = 0; nf < 2; ++nf) {
#pragma unroll
            for (int h = 0; h < 2; ++h) {
                float v0 = aw[nf][h * 2 + 0], v1 = aw[nf][h * 2 + 1];
                const int m = m0 + er + h * 8;            // kat-local 0..31
                const int kat = kt * 32 + m;
                const int n = nb0 + nf * 8 + ec;          // dh-local 0..63
                const int kh = kat >> 8;
                const size_t imgbyte = (size_t)(kh * 4 + (bid & 3)) * 65536;
                const int row = kat & 255;
                const int off = row * 128 + (((n >> 3) ^ (row & 7)) << 4) + (n & 7) * 2;
                unsigned uh, ul;
                split2(v0, v1, uh, ul);
                *(uint32_t*)((char*)g_Bimg + imgbyte + off) = uh;
                *(uint32_t*)((char*)g_Bimg + imgbyte + 32768 + off) = ul;
            }
        }
    }
}

// ---------------------------------------------------------------------------
// Persistent tensor-core GEMM: out[n][k] = sum_d X[d][n] W[d][k]
// 148 CTAs x 256 threads (8 warps, warp tile 64n x 32k = wn2 x wk4).
// 3-stage cp.async.bulk pipeline with full/empty mbarrier flow control:
// warps run ahead; only the producer lane waits for stage stragglers.
// Stage buffer (65536 B): Ahi +0, Alo +16K, Bhi +32K, Blo +48K.
// smem ctrl: full[3] @ sb+0/16/32, empty[3] @ sb+48/64/80.
// ---------------------------------------------------------------------------
#define SMEM_MMA (1024 + 3 * 65536)

__global__ __launch_bounds__(256, 1)
void out_mma_kernel(float* __restrict__ out) {
    extern __shared__ __align__(1024) char smem[];
    const uint32_t sb = smem_u32(smem);
    const uint32_t BUF0 = sb + 1024;

    const int bid = blockIdx.x;
    const int t = threadIdx.x, wid = t >> 5, lane = t & 31;
    const int wn = wid & 1;          // n-half of CTA tile (64 rows)
    const int wk = wid >> 1;         // k-quarter (32 cols)

    if (t == 0) {
        MBARRIER_INIT(sb + 0, 1);  MBARRIER_INIT(sb + 16, 1); MBARRIER_INIT(sb + 32, 1);
        MBARRIER_INIT(sb + 48, 8); MBARRIER_INIT(sb + 64, 8); MBARRIER_INIT(sb + 80, 8);
    }
    __syncthreads();

    const int nitems = (2047 - bid) / 148 + 1;
    const int nc = nitems * 4;

    auto fill = [&](int cc) {
        const int item = bid + (cc >> 2) * 148;
        const int c = cc & 3;
        const int nt = item >> 2, kq = item & 3;
        const uint32_t buf = BUF0 + (uint32_t)(cc % 3) * 65536;
        const uint32_t mb = sb + (uint32_t)(cc % 3) * 16;
        MBARRIER_EXPECT_TX(mb, 65536u);
        bulk_g2s(buf, (const char*)g_Aimg + (size_t)nt * 131072 + (size_t)c * 32768,
                 32768u, mb);
        const char* Bb = (const char*)g_Bimg + (size_t)(kq >> 1) * 262144
                       + (size_t)c * 65536 + (size_t)(kq & 1) * 16384;
        bulk_g2s(buf + 32768, Bb, 16384u, mb);
        bulk_g2s(buf + 49152, Bb + 32768, 16384u, mb);
    };
    if (t == 0) {
        fill(0);
        if (nc > 1) fill(1);
        if (nc > 2) fill(2);
    }

    const int a_row = lane & 15, a_gsel = lane >> 4;
    const int b_row = lane & 7, b_gsel = (lane >> 3) & 1;

    float acc[4][4][4];

    for (int cc = 0; cc < nc; ++cc) {
        const int c = cc & 3;
        if (c == 0) {
#pragma unroll
            for (int mf = 0; mf < 4; ++mf)
#pragma unroll
                for (int nf = 0; nf < 4; ++nf)
#pragma unroll
                    for (int q = 0; q < 4; ++q) acc[mf][nf][q] = 0.f;
        }
        const uint32_t st = (uint32_t)(cc % 3);
        MBARRIER_WAIT_PARITY(sb + st * 16, (cc / 3) & 1);
        const uint32_t buf = BUF0 + st * 65536;
        const uint32_t Ahi = buf, Alo = buf + 16384;
        const uint32_t Bhi = buf + 32768, Blo = buf + 49152;

#pragma unroll
        for (int ks = 0; ks < 4; ++ks) {
            const int g = ks * 2;
            uint32_t ah[4][4], al[4][4], bh[4][2], bl[4][2];
#pragma unroll
            for (int mf = 0; mf < 4; ++mf) {
                const int row = wn * 64 + mf * 16 + a_row;
                const uint32_t aoff = row * 128 + (((g + a_gsel) ^ (row & 7)) << 4);
                LDSM_X4(ah[mf][0], ah[mf][1], ah[mf][2], ah[mf][3], Ahi + aoff);
                LDSM_X4(al[mf][0], al[mf][1], al[mf][2], al[mf][3], Alo + aoff);
            }
#pragma unroll
            for (int nf = 0; nf < 4; ++nf) {
                const int row = wk * 32 + nf * 8 + b_row;
                const uint32_t boff = row * 128 + (((g + b_gsel) ^ (row & 7)) << 4);
                LDSM_X2(bh[nf][0], bh[nf][1], Bhi + boff);
                LDSM_X2(bl[nf][0], bl[nf][1], Blo + boff);
            }
#pragma unroll
            for (int mf = 0; mf < 4; ++mf)
#pragma unroll
                for (int nf = 0; nf < 4; ++nf) {
                    float* d = acc[mf][nf];
                    MMA_F16(d[0], d[1], d[2], d[3],
                            ah[mf][0], ah[mf][1], ah[mf][2], ah[mf][3],
                            bh[nf][0], bh[nf][1]);
                    MMA_F16(d[0], d[1], d[2], d[3],
                            ah[mf][0], ah[mf][1], ah[mf][2], ah[mf][3],
                            bl[nf][0], bl[nf][1]);
                    MMA_F16(d[0], d[1], d[2], d[3],
                            al[mf][0], al[mf][1], al[mf][2], al[mf][3],
                            bh[nf][0], bh[nf][1]);
                }
        }

        // release this stage (per-warp arrival; no CTA-wide sync)
        if (lane == 0) MBARRIER_ARRIVE(sb + 48 + st * 16);
        // producer: wait for all 8 warps to release, then refill stage
        if (t == 0 && cc + 3 < nc) {
            MBARRIER_WAIT_PARITY(sb + 48 + st * 16, (cc / 3) & 1);
            fill(cc + 3);
        }

        if (c == 3) {                    // epilogue for this item
            const int item = bid + (cc >> 2) * 148;
            const int nt = item >> 2, kq = item & 3;
            const int er = lane >> 2, ec = (lane & 3) * 2;
            const size_t nbase = (size_t)nt * 128 + wn * 64 + er;
            const int kbase = kq * 128 + wk * 32 + ec;
#pragma unroll
            for (int mf = 0; mf < 4; ++mf) {
                const size_t r0 = nbase + mf * 16;
#pragma unroll
                for (int nf = 0; nf < 4; ++nf) {
                    const int col = kbase + nf * 8;
                    float* d = acc[mf][nf];
                    *(float2*)&out[r0 * KAT + col]       = make_float2(d[0], d[1]);
                    *(float2*)&out[(r0 + 8) * KAT + col] = make_float2(d[2], d[3]);
                }
            }
        }
    }
}

// ---------------------------------------------------------------------------
// Launch: 2 graph nodes, no allocations, deterministic, replay-safe.
// ---------------------------------------------------------------------------
extern "C" void kernel_launch(void* const* d_in, const int* in_sizes, int n_in,
                              void* d_out, int out_size) {
    (void)in_sizes; (void)n_in; (void)out_size;
    const float* z_e  = (const float*)d_in[0];   // [DIMD, NCOL]
    const float* dict = (const float*)d_in[1];   // [KAT, DIMD]
    float* out = (float*)d_out;                  // [NCOL, KAT]

    cudaFuncSetAttribute(prep_kernel,
                         cudaFuncAttributeMaxDynamicSharedMemorySize, SMEM_PREP);
    cudaFuncSetAttribute(out_mma_kernel,
                         cudaFuncAttributeMaxDynamicSharedMemorySize, SMEM_MMA);

    // 1) gram + HMMA Newton-Schulz (fp16-split, 4-product) + W images,
    //    concurrent with X image convert on the other 84 SMs
    prep_kernel<<<NB + NCONV, 256, SMEM_PREP>>>(dict, z_e);

    // 2) persistent tensor-core GEMM: out = X^T W (fp16 2-split, 3 products)
    out_mma_kernel<<<148, 256, SMEM_MMA>>>(out);
}

// round 14
// speedup vs baseline: 1.1295x; 1.0218x over previous
#include <cuda_runtime.h>
#include <cuda_fp16.h>
#include <cstdint>

// Problem constants
#define DIMD 256
#define KAT  512
#define NCOL 65536
#define NB   64          // prep CTAs (barrier group)
#define NCONV 84         // converter CTAs (NB+NCONV = 148 SMs, all co-resident)
#define NDUAL 6          // dual Newton-Schulz passes (then one final Y-only pass)

// Chebyshev degree-1 start for Newton-Schulz (residual 0.865 on [30,1600])
#define A_COEF 4.57720e-3f
#define B_COEF (-2.80809e-6f)
#define NODIAG (-1000000)

// ---------------------------------------------------------------------------
// Device scratch (no allocations allowed)
// ---------------------------------------------------------------------------
__device__ float g_G[DIMD * DIMD];
__device__ float g_Y[2 * DIMD * DIMD];    // Y ping-pong
__device__ float g_Z[2 * DIMD * DIMD];    // Z = G*Y ping-pong
__device__ unsigned g_bar = 0;            // monotone grid barrier

// Pre-swizzled fp16-split images (XOR swizzle within 128B rows):
// A: per (ntile 0..511, dchunk 0..3): [split 2][128 n][64 d] = 32768 B each
__device__ __align__(1024) __half g_Aimg[512 * 4 * 2 * 8192];   // 64 MB
// B: per (img = kh*4+chunk, 8 imgs): [split 2][256 k][64 d] = 65536 B each
__device__ __align__(1024) __half g_Bimg[8 * 2 * 16384];        // 512 KB

// ---------------------------------------------------------------------------
// PTX helpers (portable PTX only — no 'a'-suffix features)
// ---------------------------------------------------------------------------
__device__ __forceinline__ uint32_t smem_u32(const void* p) {
    uint32_t a;
    asm("{ .reg .u64 tmp; cvta.to.shared.u64 tmp, %1; cvt.u32.u64 %0, tmp; }"
        : "=r"(a) : "l"(p));
    return a;
}

#define MBARRIER_INIT(addr, cnt) \
    asm volatile("mbarrier.init.shared.b64 [%0], %1;" :: "r"(addr), "r"(cnt) : "memory")
#define MBARRIER_EXPECT_TX(addr, bytes) \
    asm volatile("mbarrier.arrive.expect_tx.shared.b64 _, [%0], %1;" \
                 :: "r"(addr), "r"(bytes) : "memory")
#define MBARRIER_ARRIVE(addr) \
    asm volatile("mbarrier.arrive.shared.b64 _, [%0];" :: "r"(addr) : "memory")

#define MBARRIER_WAIT_PARITY(addr, par) do {                                   \
    uint32_t _m = (addr), _p = (par), _done;                                   \
    asm volatile("{\n\t.reg .pred p;\n\t"                                      \
        "mbarrier.try_wait.parity.acquire.cta.shared::cta.b64 p, [%1], %2;\n\t"\
        "selp.b32 %0, 1, 0, p;\n\t}"                                           \
        : "=r"(_done) : "r"(_m), "r"(_p) : "memory");                          \
    if (!_done) {                                                              \
        asm volatile("{\n\t.reg .pred P1;\n\t"                                 \
            "WL_%=:\n\t"                                                       \
            "mbarrier.try_wait.parity.acquire.cta.shared::cta.b64 P1, [%0], %1, 0x989680;\n\t" \
            "@P1 bra.uni WD_%=;\n\t"                                           \
            "bra.uni WL_%=;\n\t"                                               \
            "WD_%=:\n\t}"                                                      \
            :: "r"(_m), "r"(_p) : "memory");                                   \
    }                                                                          \
} while (0)

__device__ __forceinline__ void bulk_g2s(uint32_t dst, const void* src,
                                         uint32_t bytes, uint32_t mbar) {
    asm volatile("cp.async.bulk.shared::cta.global.mbarrier::complete_tx::bytes "
                 "[%0], [%1], %2, [%3];"
                 :: "r"(dst), "l"(src), "r"(bytes), "r"(mbar) : "memory");
}

#define LDSM_X4(r0, r1, r2, r3, a) \
    asm volatile("ldmatrix.sync.aligned.m8n8.x4.shared.b16 {%0,%1,%2,%3}, [%4];" \
        : "=r"(r0), "=r"(r1), "=r"(r2), "=r"(r3) : "r"(a))
#define LDSM_X2(r0, r1, a) \
    asm volatile("ldmatrix.sync.aligned.m8n8.x2.shared.b16 {%0,%1}, [%2];" \
        : "=r"(r0), "=r"(r1) : "r"(a))

#define MMA_F16(d0, d1, d2, d3, a0, a1, a2, a3, b0, b1) \
    asm volatile("mma.sync.aligned.m16n8k16.row.col.f32.f16.f16.f32 " \
        "{%0,%1,%2,%3}, {%4,%5,%6,%7}, {%8,%9}, {%0,%1,%2,%3};" \
        : "+f"(d0), "+f"(d1), "+f"(d2), "+f"(d3) \
        : "r"(a0), "r"(a1), "r"(a2), "r"(a3), "r"(b0), "r"(b1))

__device__ __forceinline__ unsigned short hbits(__half h) {
    return *reinterpret_cast<unsigned short*>(&h);
}

// pack two floats into one fp16x2 hi word + one fp16x2 lo word
__device__ __forceinline__ void split2(float v0, float v1, unsigned& uh, unsigned& ul) {
    __half h0 = __float2half_rn(v0);
    __half h1 = __float2half_rn(v1);
    __half l0 = __float2half_rn(v0 - __half2float(h0));
    __half l1 = __float2half_rn(v1 - __half2float(h1));
    uh = (unsigned)hbits(h0) | ((unsigned)hbits(h1) << 16);
    ul = (unsigned)hbits(l0) | ((unsigned)hbits(l1) << 16);
}

// 4-product split GEMM (hi*hi + hi*lo + lo*hi + lo*lo)
__device__ __forceinline__ void mma4(float* d, const uint32_t* ah, const uint32_t* al,
                                     const uint32_t* bh, const uint32_t* bl) {
    MMA_F16(d[0], d[1], d[2], d[3], ah[0], ah[1], ah[2], ah[3], bh[0], bh[1]);
    MMA_F16(d[0], d[1], d[2], d[3], ah[0], ah[1], ah[2], ah[3], bl[0], bl[1]);
    MMA_F16(d[0], d[1], d[2], d[3], al[0], al[1], al[2], al[3], bh[0], bh[1]);
    MMA_F16(d[0], d[1], d[2], d[3], al[0], al[1], al[2], al[3], bl[0], bl[1]);
}

// ---------------------------------------------------------------------------
// Grid barrier among the NB prep CTAs (all co-resident)
// ---------------------------------------------------------------------------
__device__ __forceinline__ void grid_barrier() {
    __syncthreads();
    if (threadIdx.x == 0) {
        __threadfence();
        unsigned t = atomicAdd(&g_bar, 1u);
        unsigned target = (t / NB + 1u) * NB;
        volatile unsigned* p = &g_bar;
        while (*p < target) { }
        __threadfence();
    }
    __syncthreads();
}

// ---------------------------------------------------------------------------
// Build a K-major fp16-split smem image from f32 rows.
//   dst: smem byte pointer; src: f32 row-major, ld = row stride (floats).
//   nrows rows x 256 cols; chunk c (64 cols) at dst + c*nrows*128,
//   lo split at +4*nrows*128. If diag_row0 != NODIAG, builds M = 2I - src.
// ---------------------------------------------------------------------------
__device__ __forceinline__ void build_img(char* dst, const float* __restrict__ src,
                                          int ld, int nrows, int diag_row0) {
    const int cstride = nrows * 128;
    const int sstride = cstride * 4;
    for (int tt = threadIdx.x; tt < nrows * 32; tt += 256) {
        const int row = tt >> 5, c0 = (tt & 31) * 8;
        float f[8];
        *(float4*)&f[0] = *(const float4*)&src[row * ld + c0];
        *(float4*)&f[4] = *(const float4*)&src[row * ld + c0 + 4];
        if (diag_row0 != NODIAG) {
            const int gr = diag_row0 + row;
#pragma unroll
            for (int j = 0; j < 8; ++j)
                f[j] = ((gr == c0 + j) ? 2.0f : 0.0f) - f[j];
        }
        unsigned uh[4], ul[4];
#pragma unroll
        for (int q = 0; q < 4; ++q)
            split2(f[2 * q], f[2 * q + 1], uh[q], ul[q]);
        const int chunk = c0 >> 6, g = (c0 & 63) >> 3;
        const int off = chunk * cstride + row * 128 + ((g ^ (row & 7)) << 4);
        *(uint4*)(dst + off) = make_uint4(uh[0], uh[1], uh[2], uh[3]);
        *(uint4*)(dst + sstride + off) = make_uint4(ul[0], ul[1], ul[2], ul[3]);
    }
}

// ---------------------------------------------------------------------------
// Prep kernel, 148 CTAs x 256 threads, 98304 B dynamic smem:
//   bid <  64 : scalar gram (+Y0) -> HMMA init/dual/final NS passes -> W imgs
//   bid >= 64 : convert X -> fp16-split swizzled A images (concurrent)
// (byte-identical to the R11 known-good prep)
// ---------------------------------------------------------------------------
#define SMEM_PREP 98304

__global__ __launch_bounds__(256, 1)
void prep_kernel(const float* __restrict__ dict, const float* __restrict__ X) {
    extern __shared__ __align__(1024) char pool[];
    const uint32_t pb = smem_u32(pool);
    const int bid = blockIdx.x;
    const int t = threadIdx.x;

    // =========================== Converter CTAs ============================
    if (bid >= NB) {
        float (*Sx)[132] = (float(*)[132])pool;
        for (int tile = bid - NB; tile < 2048; tile += NCONV) {
            const int nt = tile >> 2, c = tile & 3;
            const int nn0 = nt * 128, d0 = c * 64;
            {
                const int dl = t >> 5, n4 = (t & 31) * 4;
#pragma unroll
                for (int j = 0; j < 8; ++j) {
                    float4 v = *(const float4*)&X[(size_t)(d0 + dl + j * 8) * NCOL + nn0 + n4];
                    *(float4*)&Sx[dl + j * 8][n4] = v;
                }
            }
            __syncthreads();
            {
                const int m = t >> 1, half = t & 1;
                char* pA = (char*)g_Aimg + (size_t)tile * 32768;
#pragma unroll
                for (int gl = 0; gl < 4; ++gl) {
                    unsigned uh[4], ul[4];
#pragma unroll
                    for (int q = 0; q < 4; ++q) {
                        int i0 = gl * 8 + q * 2;
                        split2(Sx[half * 32 + i0][m], Sx[half * 32 + i0 + 1][m],
                               uh[q], ul[q]);
                    }
                    int g = half * 4 + gl;
                    int off = m * 128 + ((g ^ (m & 7)) << 4);
                    *(uint4*)(pA + off)         = make_uint4(uh[0], uh[1], uh[2], uh[3]);
                    *(uint4*)(pA + 16384 + off) = make_uint4(ul[0], ul[1], ul[2], ul[3]);
                }
            }
            __syncthreads();
        }
        return;
    }

    // ============================= Prep CTAs ===============================
    const int wid = t >> 5, lane = t & 31;
    const int i0 = (bid >> 3) * 32;      // output row tile base (NS passes)
    const int j0 = (bid & 7) * 32;       // output col tile base
    const int m0 = (wid & 1) * 16;       // warp sub-tile
    const int n0 = (wid >> 1) * 8;
    const int er = lane >> 2, ec = (lane & 3) * 2;
    const int ar = m0 + (lane & 15), ag = lane >> 4;
    const int br = n0 + (lane & 7), bg = (lane >> 3) & 1;

    // ---------------- Phase 1: scalar gram G = dict^T dict, Y0 = aI + bG ---
    {
        float (*As)[34] = (float(*)[34])pool;
        float (*Bs)[34] = (float(*)[34])(pool + 32 * 34 * 4);
        const int tx = t & 15, ty = t >> 4;
        const int lr = t >> 3, lc = (t & 7) * 4;
        float a00 = 0.f, a01 = 0.f, a10 = 0.f, a11 = 0.f;
        for (int kc = 0; kc < KAT; kc += 32) {
            float4 va = *(const float4*)&dict[(kc + lr) * DIMD + i0 + lc];
            float4 vb = *(const float4*)&dict[(kc + lr) * DIMD + j0 + lc];
            As[lr][lc + 0] = va.x; As[lr][lc + 1] = va.y;
            As[lr][lc + 2] = va.z; As[lr][lc + 3] = va.w;
            Bs[lr][lc + 0] = vb.x; Bs[lr][lc + 1] = vb.y;
            Bs[lr][lc + 2] = vb.z; Bs[lr][lc + 3] = vb.w;
            __syncthreads();
#pragma unroll
            for (int k = 0; k < 32; ++k) {
                float2 a = *(const float2*)&As[k][ty * 2];
                float2 b = *(const float2*)&Bs[k][tx * 2];
                a00 += a.x * b.x; a01 += a.x * b.y;
                a10 += a.y * b.x; a11 += a.y * b.y;
            }
            __syncthreads();
        }
        const int r0 = i0 + ty * 2, c0 = j0 + tx * 2;
        float acc[2][2] = {{a00, a01}, {a10, a11}};
#pragma unroll
        for (int ii = 0; ii < 2; ++ii)
#pragma unroll
            for (int jj = 0; jj < 2; ++jj) {
                float g = acc[ii][jj];
                g_G[(r0 + ii) * DIMD + c0 + jj] = g;
                float y0 = B_COEF * g;
                if (r0 + ii == c0 + jj) y0 += A_COEF;
                g_Y[(r0 + ii) * DIMD + c0 + jj] = y0;
            }
    }
    grid_barrier();

    // ---------------- Init pass: Z0 = a*G + b*(G*G)  (G symmetric) ---------
    {
        build_img(pool,         g_G + i0 * DIMD, DIMD, 32, NODIAG);   // A = G rows
        build_img(pool + 65536, g_G + j0 * DIMD, DIMD, 32, NODIAG);   // B = G rows (sym)
        __syncthreads();
        float ac[4] = {0.f, 0.f, 0.f, 0.f};
#pragma unroll
        for (int c = 0; c < 4; ++c) {
            const uint32_t Ab = pb + c * 4096, Bb = pb + 65536 + c * 4096;
#pragma unroll
            for (int ks = 0; ks < 4; ++ks) {
                uint32_t ah[4], al[4], bh[2], bl[2];
                uint32_t aad = Ab + ar * 128 + (((ks * 2 + ag) ^ (ar & 7)) << 4);
                LDSM_X4(ah[0], ah[1], ah[2], ah[3], aad);
                LDSM_X4(al[0], al[1], al[2], al[3], aad + 16384);
                uint32_t bad = Bb + br * 128 + (((ks * 2 + bg) ^ (br & 7)) << 4);
                LDSM_X2(bh[0], bh[1], bad);
                LDSM_X2(bl[0], bl[1], bad + 16384);
                mma4(ac, ah, al, bh, bl);
            }
        }
        const int r0 = i0 + m0 + er, c0 = j0 + n0 + ec;
        g_Z[r0 * DIMD + c0]           = A_COEF * g_G[r0 * DIMD + c0]           + B_COEF * ac[0];
        g_Z[r0 * DIMD + c0 + 1]       = A_COEF * g_G[r0 * DIMD + c0 + 1]       + B_COEF * ac[1];
        g_Z[(r0 + 8) * DIMD + c0]     = A_COEF * g_G[(r0 + 8) * DIMD + c0]     + B_COEF * ac[2];
        g_Z[(r0 + 8) * DIMD + c0 + 1] = A_COEF * g_G[(r0 + 8) * DIMD + c0 + 1] + B_COEF * ac[3];
    }
    grid_barrier();

    // ---------------- Dual NS passes: Y' = Y*M, Z' = Z*M,  M = 2I - Z ------
    int p = 0;
    for (int it = 0; it < NDUAL; ++it) {
        const float* Yp = g_Y + p * DIMD * DIMD;
        const float* Zp = g_Z + p * DIMD * DIMD;
        build_img(pool,         Yp + i0 * DIMD, DIMD, 32, NODIAG);  // A1 = Y rows
        build_img(pool + 32768, Zp + i0 * DIMD, DIMD, 32, NODIAG);  // A2 = Z rows
        build_img(pool + 65536, Zp + j0 * DIMD, DIMD, 32, j0);      // B = M rows (sym)
        __syncthreads();
        float aY[4] = {0.f, 0.f, 0.f, 0.f};
        float aZ[4] = {0.f, 0.f, 0.f, 0.f};
#pragma unroll
        for (int c = 0; c < 4; ++c) {
            const uint32_t A1 = pb + c * 4096;
            const uint32_t A2 = pb + 32768 + c * 4096;
            const uint32_t Bb = pb + 65536 + c * 4096;
#pragma unroll
            for (int ks = 0; ks < 4; ++ks) {
                uint32_t ah[4], al[4], zh[4], zl[4], bh[2], bl[2];
                const uint32_t aoff = ar * 128 + (((ks * 2 + ag) ^ (ar & 7)) << 4);
                LDSM_X4(ah[0], ah[1], ah[2], ah[3], A1 + aoff);
                LDSM_X4(al[0], al[1], al[2], al[3], A1 + aoff + 16384);
                LDSM_X4(zh[0], zh[1], zh[2], zh[3], A2 + aoff);
                LDSM_X4(zl[0], zl[1], zl[2], zl[3], A2 + aoff + 16384);
                uint32_t bad = Bb + br * 128 + (((ks * 2 + bg) ^ (br & 7)) << 4);
                LDSM_X2(bh[0], bh[1], bad);
                LDSM_X2(bl[0], bl[1], bad + 16384);
                mma4(aY, ah, al, bh, bl);
                mma4(aZ, zh, zl, bh, bl);
            }
        }
        float* Yn = g_Y + (p ^ 1) * DIMD * DIMD;
        float* Zn = g_Z + (p ^ 1) * DIMD * DIMD;
        const int r0 = i0 + m0 + er, c0 = j0 + n0 + ec;
        Yn[r0 * DIMD + c0] = aY[0];           Yn[r0 * DIMD + c0 + 1] = aY[1];
        Yn[(r0 + 8) * DIMD + c0] = aY[2];     Yn[(r0 + 8) * DIMD + c0 + 1] = aY[3];
        Zn[r0 * DIMD + c0] = aZ[0];           Zn[r0 * DIMD + c0 + 1] = aZ[1];
        Zn[(r0 + 8) * DIMD + c0] = aZ[2];     Zn[(r0 + 8) * DIMD + c0 + 1] = aZ[3];
        grid_barrier();
        p ^= 1;
    }

    // ---------------- Final pass: Yf = Y*(2I - Z) --------------------------
    {
        const float* Yp = g_Y + p * DIMD * DIMD;
        const float* Zp = g_Z + p * DIMD * DIMD;
        build_img(pool,         Yp + i0 * DIMD, DIMD, 32, NODIAG);
        build_img(pool + 65536, Zp + j0 * DIMD, DIMD, 32, j0);
        __syncthreads();
        float ac[4] = {0.f, 0.f, 0.f, 0.f};
#pragma unroll
        for (int c = 0; c < 4; ++c) {
            const uint32_t Ab = pb + c * 4096, Bb = pb + 65536 + c * 4096;
#pragma unroll
            for (int ks = 0; ks < 4; ++ks) {
                uint32_t ah[4], al[4], bh[2], bl[2];
                uint32_t aad = Ab + ar * 128 + (((ks * 2 + ag) ^ (ar & 7)) << 4);
                LDSM_X4(ah[0], ah[1], ah[2], ah[3], aad);
                LDSM_X4(al[0], al[1], al[2], al[3], aad + 16384);
                uint32_t bad = Bb + br * 128 + (((ks * 2 + bg) ^ (br & 7)) << 4);
                LDSM_X2(bh[0], bh[1], bad);
                LDSM_X2(bl[0], bl[1], bad + 16384);
                mma4(ac, ah, al, bh, bl);
            }
        }
        float* Yn = g_Y + (p ^ 1) * DIMD * DIMD;
        const int r0 = i0 + m0 + er, c0 = j0 + n0 + ec;
        Yn[r0 * DIMD + c0] = ac[0];           Yn[r0 * DIMD + c0 + 1] = ac[1];
        Yn[(r0 + 8) * DIMD + c0] = ac[2];     Yn[(r0 + 8) * DIMD + c0 + 1] = ac[3];
    }
    grid_barrier();
    p ^= 1;

    // ---------------- W pass: C[kat][dh] = sum_e dict[kat][e]*Yf[dh][e] ----
    // Output 32 kat x 64 dh per CTA, written straight into g_Bimg (split+swizzled).
    {
        const float* Yf = g_Y + p * DIMD * DIMD;
        const int kt = bid >> 2, dbase = (bid & 3) * 64;
        build_img(pool,         dict + (size_t)kt * 32 * DIMD, DIMD, 32, NODIAG); // A = dict rows
        build_img(pool + 32768, Yf + dbase * DIMD, DIMD, 64, NODIAG);             // B = Yf rows
        __syncthreads();
        const int nb0 = (wid >> 1) * 16;
        float aw[2][4] = {{0.f, 0.f, 0.f, 0.f}, {0.f, 0.f, 0.f, 0.f}};
#pragma unroll
        for (int c = 0; c < 4; ++c) {
            const uint32_t Ab = pb + c * 4096;
            const uint32_t Bb = pb + 32768 + c * 8192;
#pragma unroll
            for (int ks = 0; ks < 4; ++ks) {
                uint32_t ah[4], al[4];
                uint32_t aad = Ab + ar * 128 + (((ks * 2 + ag) ^ (ar & 7)) << 4);
                LDSM_X4(ah[0], ah[1], ah[2], ah[3], aad);
                LDSM_X4(al[0], al[1], al[2], al[3], aad + 16384);
#pragma unroll
                for (int nf = 0; nf < 2; ++nf) {
                    const int brw = nb0 + nf * 8 + (lane & 7);
                    uint32_t bh[2], bl[2];
                    uint32_t bad = Bb + brw * 128 + (((ks * 2 + bg) ^ (brw & 7)) << 4);
                    LDSM_X2(bh[0], bh[1], bad);
                    LDSM_X2(bl[0], bl[1], bad + 32768);
                    mma4(aw[nf], ah, al, bh, bl);
                }
            }
        }
        // Epilogue: write fp16-split swizzled g_Bimg
#pragma unroll
        for (int nf = 0; nf < 2; ++nf) {
#pragma unroll
            for (int h = 0; h < 2; ++h) {
                float v0 = aw[nf][h * 2 + 0], v1 = aw[nf][h * 2 + 1];
                const int m = m0 + er + h * 8;            // kat-local 0..31
                const int kat = kt * 32 + m;
                const int n = nb0 + nf * 8 + ec;          // dh-local 0..63
                const int kh = kat >> 8;
                const size_t imgbyte = (size_t)(kh * 4 + (bid & 3)) * 65536;
                const int row = kat & 255;
                const int off = row * 128 + (((n >> 3) ^ (row & 7)) << 4) + (n & 7) * 2;
                unsigned uh, ul;
                split2(v0, v1, uh, ul);
                *(uint32_t*)((char*)g_Bimg + imgbyte + off) = uh;
                *(uint32_t*)((char*)g_Bimg + imgbyte + 32768 + off) = ul;
            }
        }
    }
}

// ---------------------------------------------------------------------------
// Fragment loader for out_mma: loads one ks-step's A/B hi+lo fragments.
// ---------------------------------------------------------------------------
__device__ __forceinline__ void load_frags(
    uint32_t (*ahd)[4], uint32_t (*ald)[4], uint32_t (*bhd)[2], uint32_t (*bld)[2],
    int gg, uint32_t Ahi, uint32_t Alo, uint32_t Bhi, uint32_t Blo,
    int wn, int wk, int a_row, int a_gsel, int b_row, int b_gsel) {
#pragma unroll
    for (int mf = 0; mf < 4; ++mf) {
        const int row = wn * 64 + mf * 16 + a_row;
        const uint32_t aoff = row * 128 + (((gg + a_gsel) ^ (row & 7)) << 4);
        LDSM_X4(ahd[mf][0], ahd[mf][1], ahd[mf][2], ahd[mf][3], Ahi + aoff);
        LDSM_X4(ald[mf][0], ald[mf][1], ald[mf][2], ald[mf][3], Alo + aoff);
    }
#pragma unroll
    for (int nf = 0; nf < 4; ++nf) {
        const int row = wk * 32 + nf * 8 + b_row;
        const uint32_t boff = row * 128 + (((gg + b_gsel) ^ (row & 7)) << 4);
        LDSM_X2(bhd[nf][0], bhd[nf][1], Bhi + boff);
        LDSM_X2(bld[nf][0], bld[nf][1], Blo + boff);
    }
}

// ---------------------------------------------------------------------------
// Persistent tensor-core GEMM: out[n][k] = sum_d X[d][n] W[d][k]
// 148 CTAs x 256 threads (8 warps, warp tile 64n x 32k).
// 3-stage cp.async.bulk pipeline + mbarrier flow control + register-level
// fragment double-buffering (ONLY change vs the R11 known-good kernel).
// Stage buffer (65536 B): Ahi +0, Alo +16K, Bhi +32K, Blo +48K.
// ---------------------------------------------------------------------------
#define SMEM_MMA (1024 + 3 * 65536)

__global__ __launch_bounds__(256, 1)
void out_mma_kernel(float* __restrict__ out) {
    extern __shared__ __align__(1024) char smem[];
    const uint32_t sb = smem_u32(smem);
    const uint32_t BUF0 = sb + 1024;

    const int bid = blockIdx.x;
    const int t = threadIdx.x, wid = t >> 5, lane = t & 31;
    const int wn = wid & 1;          // n-half of CTA tile (64 rows)
    const int wk = wid >> 1;         // k-quarter (32 cols)

    if (t == 0) {
        MBARRIER_INIT(sb + 0, 1);  MBARRIER_INIT(sb + 16, 1); MBARRIER_INIT(sb + 32, 1);
        MBARRIER_INIT(sb + 48, 8); MBARRIER_INIT(sb + 64, 8); MBARRIER_INIT(sb + 80, 8);
    }
    __syncthreads();

    const int nitems = (2047 - bid) / 148 + 1;
    const int nc = nitems * 4;

    auto fill = [&](int cc) {
        const int item = bid + (cc >> 2) * 148;
        const int c = cc & 3;
        const int nt = item >> 2, kq = item & 3;
        const uint32_t buf = BUF0 + (uint32_t)(cc % 3) * 65536;
        const uint32_t mb = sb + (uint32_t)(cc % 3) * 16;
        MBARRIER_EXPECT_TX(mb, 65536u);
        bulk_g2s(buf, (const char*)g_Aimg + (size_t)nt * 131072 + (size_t)c * 32768,
                 32768u, mb);
        const char* Bb = (const char*)g_Bimg + (size_t)(kq >> 1) * 262144
                       + (size_t)c * 65536 + (size_t)(kq & 1) * 16384;
        bulk_g2s(buf + 32768, Bb, 16384u, mb);
        bulk_g2s(buf + 49152, Bb + 32768, 16384u, mb);
    };
    if (t == 0) {
        fill(0);
        if (nc > 1) fill(1);
        if (nc > 2) fill(2);
    }

    const int a_row = lane & 15, a_gsel = lane >> 4;
    const int b_row = lane & 7, b_gsel = (lane >> 3) & 1;

    float acc[4][4][4];
    uint32_t ah[2][4][4], al[2][4][4], bh[2][4][2], bl[2][4][2];

    for (int cc = 0; cc < nc; ++cc) {
        const int c = cc & 3;
        if (c == 0) {
#pragma unroll
            for (int mf = 0; mf < 4; ++mf)
#pragma unroll
                for (int nf = 0; nf < 4; ++nf)
#pragma unroll
                    for (int q = 0; q < 4; ++q) acc[mf][nf][q] = 0.f;
        }
        const uint32_t st = (uint32_t)(cc % 3);
        MBARRIER_WAIT_PARITY(sb + st * 16, (cc / 3) & 1);
        const uint32_t buf = BUF0 + st * 65536;
        const uint32_t Ahi = buf, Alo = buf + 16384;
        const uint32_t Bhi = buf + 32768, Blo = buf + 49152;

        // prologue: fragments for ks=0
        load_frags(ah[0], al[0], bh[0], bl[0], 0, Ahi, Alo, Bhi, Blo,
                   wn, wk, a_row, a_gsel, b_row, b_gsel);

#pragma unroll
        for (int ks = 0; ks < 4; ++ks) {
            const int cb = ks & 1;
            // prefetch next ks fragments under the MMA shadow
            if (ks < 3)
                load_frags(ah[cb ^ 1], al[cb ^ 1], bh[cb ^ 1], bl[cb ^ 1],
                           (ks + 1) * 2, Ahi, Alo, Bhi, Blo,
                           wn, wk, a_row, a_gsel, b_row, b_gsel);
#pragma unroll
            for (int mf = 0; mf < 4; ++mf)
#pragma unroll
                for (int nf = 0; nf < 4; ++nf) {
                    float* d = acc[mf][nf];
                    MMA_F16(d[0], d[1], d[2], d[3],
                            ah[cb][mf][0], ah[cb][mf][1], ah[cb][mf][2], ah[cb][mf][3],
                            bh[cb][nf][0], bh[cb][nf][1]);
                    MMA_F16(d[0], d[1], d[2], d[3],
                            ah[cb][mf][0], ah[cb][mf][1], ah[cb][mf][2], ah[cb][mf][3],
                            bl[cb][nf][0], bl[cb][nf][1]);
                    MMA_F16(d[0], d[1], d[2], d[3],
                            al[cb][mf][0], al[cb][mf][1], al[cb][mf][2], al[cb][mf][3],
                            bh[cb][nf][0], bh[cb][nf][1]);
                }
        }

        // release this stage (per-warp arrival; no CTA-wide sync)
        if (lane == 0) MBARRIER_ARRIVE(sb + 48 + st * 16);
        // producer: wait for all 8 warps to release, then refill stage
        if (t == 0 && cc + 3 < nc) {
            MBARRIER_WAIT_PARITY(sb + 48 + st * 16, (cc / 3) & 1);
            fill(cc + 3);
        }

        if (c == 3) {                    // epilogue for this item
            const int item = bid + (cc >> 2) * 148;
            const int nt = item >> 2, kq = item & 3;
            const int er = lane >> 2, ec = (lane & 3) * 2;
            const size_t nbase = (size_t)nt * 128 + wn * 64 + er;
            const int kbase = kq * 128 + wk * 32 + ec;
#pragma unroll
            for (int mf = 0; mf < 4; ++mf) {
                const size_t r0 = nbase + mf * 16;
#pragma unroll
                for (int nf = 0; nf < 4; ++nf) {
                    const int col = kbase + nf * 8;
                    float* d = acc[mf][nf];
                    *(float2*)&out[r0 * KAT + col]       = make_float2(d[0], d[1]);
                    *(float2*)&out[(r0 + 8) * KAT + col] = make_float2(d[2], d[3]);
                }
            }
        }
    }
}

// ---------------------------------------------------------------------------
// Launch: 2 graph nodes, no allocations, deterministic, replay-safe.
// ---------------------------------------------------------------------------
extern "C" void kernel_launch(void* const* d_in, const int* in_sizes, int n_in,
                              void* d_out, int out_size) {
    (void)in_sizes; (void)n_in; (void)out_size;
    const float* z_e  = (const float*)d_in[0];   // [DIMD, NCOL]
    const float* dict = (const float*)d_in[1];   // [KAT, DIMD]
    float* out = (float*)d_out;                  // [NCOL, KAT]

    cudaFuncSetAttribute(prep_kernel,
                         cudaFuncAttributeMaxDynamicSharedMemorySize, SMEM_PREP);
    cudaFuncSetAttribute(out_mma_kernel,
                         cudaFuncAttributeMaxDynamicSharedMemorySize, SMEM_MMA);

    // 1) R11 known-good prep: gram + deg1-Chebyshev + 6 dual NS + final + W imgs,
    //    concurrent with X image convert on the other 84 SMs
    prep_kernel<<<NB + NCONV, 256, SMEM_PREP>>>(dict, z_e);

    // 2) persistent tensor-core GEMM (fp16 2-split, 3 products) with
    //    register-level fragment double-buffering — the single change this round
    out_mma_kernel<<<148, 256, SMEM_MMA>>>(out);
}